// round 11
// baseline (speedup 1.0000x reference)
#include <cuda_runtime.h>
#include <math.h>

// Fixed-shape problem: N=16384, D=8, pid in [0,2000), K=128, R=1
#define NMAX    16384
#define NPIDMAX 2048
#define KSEL2   129     // top-(K+1) including self (self weight = 0)
#define CPT     4       // condensation points per repulsion block
#define RT      256     // threads per block
#define NBINS   258     // bins over scaled D2=256*d2: 0..257
#define BCAP    640     // candidate capacity per CP
#define SMIN    48      // sample-cum threshold (1/8 sampling)
#define INR_KEY 0x43800000u  // float bits of 256.0f (scaled radius^2)

// -------- device scratch (small, allocation-free) --------
__device__ unsigned long long g_best[NPIDMAX];
__device__ float  g_q[NMAX];
__device__ float  g_n2[NMAX];
__device__ float4 g_xp[NMAX * 2];
__device__ int    g_cplist[NPIDMAX];
__device__ int    g_cpcount;
__device__ double g_att;
__device__ double g_rep;
__device__ int    g_maskcnt;

// predicated shared histogram increment (no branch; all regs defined)
__device__ __forceinline__ void hist_add(unsigned smem_addr, float D2, float thr) {
    asm volatile(
        "{\n\t.reg .pred p;\n\t"
        "setp.le.f32 p, %1, %2;\n\t"
        "@p red.shared.add.u32 [%0], 1;\n\t}"
        :: "r"(smem_addr), "f"(D2), "f"(thr) : "memory");
}

// predicated append of j when D2 <= thr; pos pre-initialized so no undefined reads
__device__ __forceinline__ void cand_append(float D2, float thr, unsigned cnt_addr,
                                            unsigned base_addr, int j) {
    asm volatile(
        "{\n\t.reg .pred p, q;\n\t.reg .u32 pos;\n\t"
        "mov.u32 pos, %5;\n\t"                       // pos = BCAP (defined default)
        "setp.le.f32 p, %0, %1;\n\t"
        "@p atom.shared.add.u32 pos, [%2], 1;\n\t"
        "setp.lt.u32 q, pos, %5;\n\t"
        "@q mad.lo.u32 pos, pos, 4, %3;\n\t"
        "@q st.shared.u32 [pos], %4;\n\t}"
        :: "f"(D2), "f"(thr), "r"(cnt_addr), "r"(base_addr), "r"(j), "r"(BCAP)
        : "memory");
}

__global__ void k_init() {
    int i = blockIdx.x * blockDim.x + threadIdx.x;
    if (i < NPIDMAX) g_best[i] = 0ULL;
    if (i == 0) { g_cpcount = 0; g_att = 0.0; g_rep = 0.0; g_maskcnt = 0; }
}

__global__ void k_bestq(const float* __restrict__ beta, const int* __restrict__ pid,
                        const float* __restrict__ x, int N) {
    int i = blockIdx.x * blockDim.x + threadIdx.x;
    if (i >= N) return;
    float b = beta[i];
    float t = atanhf(b);
    g_q[i] = t * t + 0.01f;
    float4 v0 = *(const float4*)(x + (size_t)i * 8);
    float4 v1 = *(const float4*)(x + (size_t)i * 8 + 4);
    float n2 = v0.x * v0.x + v0.y * v0.y + v0.z * v0.z + v0.w * v0.w
             + v1.x * v1.x + v1.y * v1.y + v1.z * v1.z + v1.w * v1.w;
    g_n2[i] = n2;
    g_xp[2 * i + 0] = v0;
    g_xp[2 * i + 1] = v1;
    int p = pid[i];
    if (p > 0 && p < NPIDMAX) {
        unsigned long long key =
            ((unsigned long long)__float_as_uint(b) << 32) |
            (unsigned long long)(0xFFFFFFFFu - (unsigned)i);
        atomicMax(&g_best[p], key);
    }
}

__global__ void k_attract(const float* __restrict__ x, const int* __restrict__ pid,
                          const int* __restrict__ recon, const float* __restrict__ pt,
                          const float* __restrict__ eta, int N) {
    int i = blockIdx.x * blockDim.x + threadIdx.x;
    if (i > 0 && i < NPIDMAX) {
        unsigned long long key = g_best[i];
        if (key != 0ULL) {
            int idx = (int)(0xFFFFFFFFu - (unsigned)(key & 0xFFFFFFFFull));
            int pos = atomicAdd(&g_cpcount, 1);
            g_cplist[pos] = idx;
        }
    }
    float va = 0.0f; int m = 0;
    if (i < N) {
        int p = pid[i];
        if (p > 0 && pt[i] > 0.9f && recon[i] > 0 && fabsf(eta[i]) < 4.0f) {
            unsigned long long key = g_best[p];
            int a = (int)(0xFFFFFFFFu - (unsigned)(key & 0xFFFFFFFFull));
            const float4* xi = (const float4*)(x + (size_t)i * 8);
            const float4* xa = (const float4*)(x + (size_t)a * 8);
            float4 i0 = xi[0], i1 = xi[1], a0 = xa[0], a1 = xa[1];
            float d, d2 = 0.0f;
            d = i0.x - a0.x; d2 += d * d;
            d = i0.y - a0.y; d2 += d * d;
            d = i0.z - a0.z; d2 += d * d;
            d = i0.w - a0.w; d2 += d * d;
            d = i1.x - a1.x; d2 += d * d;
            d = i1.y - a1.y; d2 += d * d;
            d = i1.z - a1.z; d2 += d * d;
            d = i1.w - a1.w; d2 += d * d;
            va = d2 * g_q[i] * g_q[a];
            m = 1;
        }
    }
    #pragma unroll
    for (int o = 16; o; o >>= 1) {
        va += __shfl_down_sync(0xFFFFFFFFu, va, o);
        m  += __shfl_down_sync(0xFFFFFFFFu, m,  o);
    }
    if ((threadIdx.x & 31) == 0 && (m || va != 0.0f)) {
        atomicAdd(&g_att, (double)va);
        atomicAdd(&g_maskcnt, m);
    }
}

// D2 = 256*d2 via scaled registers; same expression everywhere for bit-consistency
#define D2_CHAIN(c)                                   \
    float D2 = fmaf(v0.x, m2x[c][0], n2cs[c]);        \
    D2 = fmaf(v0.y, m2x[c][1], D2);                   \
    D2 = fmaf(v0.z, m2x[c][2], D2);                   \
    D2 = fmaf(v0.w, m2x[c][3], D2);                   \
    D2 = fmaf(v1.x, m2x[c][4], D2);                   \
    D2 = fmaf(v1.y, m2x[c][5], D2);                   \
    D2 = fmaf(v1.z, m2x[c][6], D2);                   \
    D2 = fmaf(v1.w, m2x[c][7], D2);                   \
    D2 = fmaf(n2j, 256.0f, D2);

__global__ void __launch_bounds__(RT, 4) k_repulse(const int* __restrict__ pid, int N) {
    __shared__ int      s_hist[CPT][NBINS];
    __shared__ int      s_bj[CPT][BCAP];
    __shared__ unsigned s_bk[CPT][BCAP];
    __shared__ int      s_bcnt[CPT];
    __shared__ float    s_fT[CPT];
    __shared__ int      s_B2, s_cumb, s_need;
    __shared__ float    s_qc[CPT];
    __shared__ int      s_pidc[CPT];
    __shared__ float    s_red[RT / 32];

    int tid   = threadIdx.x;
    int ncp   = g_cpcount;
    int cbase = blockIdx.x * CPT;
    if (cbase >= ncp) return;

    // register-resident scaled CP data: m2x = -512*xc, n2cs = 256*|xc|^2
    float m2x[CPT][8], n2cs[CPT];
    #pragma unroll
    for (int c = 0; c < CPT; c++) {
        int slot = cbase + c;
        bool act = slot < ncp;
        int ci = act ? g_cplist[slot] : 0;
        float4 p0 = g_xp[2 * ci + 0];
        float4 p1 = g_xp[2 * ci + 1];
        m2x[c][0] = -512.0f * p0.x; m2x[c][1] = -512.0f * p0.y;
        m2x[c][2] = -512.0f * p0.z; m2x[c][3] = -512.0f * p0.w;
        m2x[c][4] = -512.0f * p1.x; m2x[c][5] = -512.0f * p1.y;
        m2x[c][6] = -512.0f * p1.z; m2x[c][7] = -512.0f * p1.w;
        n2cs[c] = act ? 256.0f * g_n2[ci] : 1e30f;
        if (tid == 0) {
            s_pidc[c] = act ? pid[ci] : -1;
            s_qc[c]   = act ? g_q[ci] : 0.0f;
        }
    }

    unsigned histb[CPT], cntb[CPT], bjb[CPT];
    #pragma unroll
    for (int c = 0; c < CPT; c++) {
        histb[c] = (unsigned)__cvta_generic_to_shared(&s_hist[c][0]);
        cntb[c]  = (unsigned)__cvta_generic_to_shared(&s_bcnt[c]);
        bjb[c]   = (unsigned)__cvta_generic_to_shared(&s_bj[c][0]);
    }

    for (int h = tid; h < CPT * NBINS; h += RT) ((int*)s_hist)[h] = 0;
    if (tid < CPT) s_bcnt[tid] = 0;
    __syncthreads();

    // ---- Phase S: 1/8-sampled histogram ----
    #pragma unroll
    for (int k = 0; k < 8; k++) {
        int j = (k << 11) + tid;
        float4 v0 = g_xp[2 * j + 0];
        float4 v1 = g_xp[2 * j + 1];
        float n2j = g_n2[j];
        #pragma unroll
        for (int c = 0; c < CPT; c++) {
            D2_CHAIN(c)
            int bb = (int)fmaxf(D2, 0.0f);
            hist_add(histb[c] + ((unsigned)bb << 2), D2, 256.0f);
        }
    }
    __syncthreads();

    // ---- threshold select per CP ----
    if (tid < CPT) {
        int cum = 0, B = 257;
        for (int b = 0; b <= 256; b++) {
            cum += s_hist[tid][b];
            if (cum >= SMIN) { B = b; break; }
        }
        s_fT[tid] = (B >= 256) ? 257.0f : (float)(B + 1);
    }
    __syncthreads();
    float fTr[CPT];
    #pragma unroll
    for (int c = 0; c < CPT; c++) fTr[c] = s_fT[c];

    // ---- Phase B: single full pass, append candidate j's ----
    for (int j = tid; j < N; j += RT) {
        float4 v0 = g_xp[2 * j + 0];
        float4 v1 = g_xp[2 * j + 1];
        float n2j = g_n2[j];
        #pragma unroll
        for (int c = 0; c < CPT; c++) {
            D2_CHAIN(c)
            cand_append(D2, fTr[c], cntb[c], bjb[c], j);
        }
    }
    __syncthreads();

    // ---- fallback (rare): exact redo for CPs where sampling failed ----
    for (int c = 0; c < CPT; c++) {
        __syncthreads();
        if (tid == 0) {
            int m = s_bcnt[c];
            s_need = (m > BCAP) || (m < KSEL2 && s_fT[c] < 257.0f);
        }
        __syncthreads();
        if (s_need) {
            for (int h = tid; h < NBINS; h += RT) s_hist[c][h] = 0;
            __syncthreads();
            for (int j = tid; j < N; j += RT) {
                float4 v0 = g_xp[2 * j + 0];
                float4 v1 = g_xp[2 * j + 1];
                float n2j = g_n2[j];
                D2_CHAIN(c)
                int bb = (int)fmaxf(D2, 0.0f);
                hist_add(histb[c] + ((unsigned)bb << 2), D2, 256.0f);
            }
            __syncthreads();
            if (tid == 0) {
                int cum = 0, B = 257;
                for (int b = 0; b <= 256; b++) {
                    cum += s_hist[c][b];
                    if (cum >= KSEL2) { B = b; break; }
                }
                s_fT[c] = (B >= 256) ? 257.0f : (float)(B + 1);
                s_bcnt[c] = 0;
            }
            __syncthreads();
            float fTc = s_fT[c];
            for (int j = tid; j < N; j += RT) {
                float4 v0 = g_xp[2 * j + 0];
                float4 v1 = g_xp[2 * j + 1];
                float n2j = g_n2[j];
                D2_CHAIN(c)
                cand_append(D2, fTc, cntb[c], bjb[c], j);
            }
            __syncthreads();
        }
    }

    // ---- final exact selection per CP over candidates ----
    for (int c = 0; c < CPT; c++) {
        int m = min(s_bcnt[c], BCAP);
        for (int h = tid; h < NBINS; h += RT) s_hist[c][h] = 0;
        __syncthreads();
        // recompute keys (identical chain) + exact candidate histogram
        for (int e = tid; e < m; e += RT) {
            int j = s_bj[c][e];
            float4 v0 = g_xp[2 * j + 0];
            float4 v1 = g_xp[2 * j + 1];
            float n2j = g_n2[j];
            D2_CHAIN(c)
            float D2c = fmaxf(D2, 0.0f);
            s_bk[c][e] = __float_as_uint(D2c);
            atomicAdd(&s_hist[c][(int)D2c], 1);
        }
        __syncthreads();
        if (tid == 0) {
            int cum = 0, B2 = NBINS, cb = 0;
            for (int b = 0; b < NBINS; b++) {
                int nc = cum + s_hist[c][b];
                if (nc >= KSEL2) { B2 = b; cb = cum; break; }
                cum = nc;
            }
            s_B2 = B2; s_cumb = cb;
        }
        __syncthreads();
        int B2 = s_B2;
        float part = 0.0f;
        for (int e = tid; e < m; e += RT) {
            unsigned key = s_bk[c][e];
            int bb = (int)__uint_as_float(key);
            bool sel = (bb < B2);
            if (bb == B2) {
                int je = s_bj[c][e];
                int rank = s_cumb;
                for (int k = 0; k < m; k++) {
                    unsigned kk = s_bk[c][k];
                    if ((int)__uint_as_float(kk) == B2)
                        rank += (kk < key) || (kk == key && s_bj[c][k] < je);
                }
                sel = (rank < KSEL2);
            }
            if (sel && key <= INR_KEY) {
                int j = s_bj[c][e];
                if (pid[j] != s_pidc[c]) {
                    float d2 = __uint_as_float(key) * 0.00390625f;  // /256
                    part += (1.0f - sqrtf(d2)) * g_q[j];
                }
            }
        }
        #pragma unroll
        for (int o = 16; o; o >>= 1) part += __shfl_down_sync(0xFFFFFFFFu, part, o);
        if ((tid & 31) == 0) s_red[tid >> 5] = part;
        __syncthreads();
        if (tid == 0) {
            float tot = 0.0f;
            #pragma unroll
            for (int w = 0; w < RT / 32; w++) tot += s_red[w];
            if (tot != 0.0f) atomicAdd(&g_rep, (double)(tot * s_qc[c]));
        }
        __syncthreads();
    }
}

__global__ void k_final(float* out, int N) {
    if (blockIdx.x == 0 && threadIdx.x == 0) {
        int mc = g_maskcnt;
        out[0] = (float)(mc > 0 ? g_att / (double)mc : 0.0);
        out[1] = (float)(g_rep / (double)N);
        out[2] = 0.0f;
        out[3] = 0.0f;
    }
}

extern "C" void kernel_launch(void* const* d_in, const int* in_sizes, int n_in,
                              void* d_out, int out_size) {
    const float* beta  = (const float*)d_in[0];
    const float* x     = (const float*)d_in[1];
    const int*   pid   = (const int*)d_in[2];
    const int*   recon = (const int*)d_in[3];
    const float* pt    = (const float*)d_in[4];
    const float* eta   = (const float*)d_in[5];
    float* out = (float*)d_out;
    int N = in_sizes[0];

    k_init<<<(NPIDMAX + 255) / 256, 256>>>();
    k_bestq<<<(N + 255) / 256, 256>>>(beta, pid, x, N);
    k_attract<<<(N + 127) / 128, 128>>>(x, pid, recon, pt, eta, N);
    int ngrp = (NPIDMAX + CPT - 1) / CPT;   // 512 blocks
    k_repulse<<<ngrp, RT>>>(pid, N);
    k_final<<<1, 32>>>(out, N);
}

// round 12
// speedup vs baseline: 1.6211x; 1.6211x over previous
#include <cuda_runtime.h>
#include <math.h>

// Fixed-shape problem: N=16384, D=8, pid in [0,2000), K=128, R=1
#define NMAX    16384
#define NPIDMAX 2048
#define KSEL2   129     // top-(K+1) including self (self weight = 0)
#define CPT     4       // condensation points per repulsion block
#define RT      256     // threads per block
#define NB      256     // histogram bins over D2=256*d2 in [0,256]
#define BCAP    128     // boundary-bin candidate capacity per CP

// -------- device scratch (small, allocation-free) --------
__device__ unsigned long long g_best[NPIDMAX];
__device__ float  g_q[NMAX];
__device__ float  g_n2[NMAX];
__device__ float4 g_xp[NMAX * 2];
__device__ int    g_cplist[NPIDMAX];
__device__ int    g_cpcount;
__device__ double g_att;
__device__ double g_rep;
__device__ int    g_maskcnt;

// predicated shared histogram increment (no branch)
__device__ __forceinline__ void hist_add(unsigned smem_addr, float D2) {
    asm volatile(
        "{\n\t.reg .pred p;\n\t"
        "setp.le.f32 p, %1, 0f43800000;\n\t"   // D2 <= 256.0f
        "@p red.shared.add.u32 [%0], 1;\n\t}"
        :: "r"(smem_addr), "f"(D2) : "memory");
}

__global__ void k_init() {
    int i = blockIdx.x * blockDim.x + threadIdx.x;
    if (i < NPIDMAX) g_best[i] = 0ULL;
    if (i == 0) { g_cpcount = 0; g_att = 0.0; g_rep = 0.0; g_maskcnt = 0; }
}

__global__ void k_bestq(const float* __restrict__ beta, const int* __restrict__ pid,
                        const float* __restrict__ x, int N) {
    int i = blockIdx.x * blockDim.x + threadIdx.x;
    if (i >= N) return;
    float b = beta[i];
    float t = atanhf(b);
    g_q[i] = t * t + 0.01f;
    float4 v0 = *(const float4*)(x + (size_t)i * 8);
    float4 v1 = *(const float4*)(x + (size_t)i * 8 + 4);
    float n2 = v0.x * v0.x + v0.y * v0.y + v0.z * v0.z + v0.w * v0.w
             + v1.x * v1.x + v1.y * v1.y + v1.z * v1.z + v1.w * v1.w;
    g_n2[i] = n2;
    g_xp[2 * i + 0] = v0;
    g_xp[2 * i + 1] = v1;
    int p = pid[i];
    if (p > 0 && p < NPIDMAX) {
        unsigned long long key =
            ((unsigned long long)__float_as_uint(b) << 32) |
            (unsigned long long)(0xFFFFFFFFu - (unsigned)i);
        atomicMax(&g_best[p], key);
    }
}

__global__ void k_attract(const float* __restrict__ x, const int* __restrict__ pid,
                          const int* __restrict__ recon, const float* __restrict__ pt,
                          const float* __restrict__ eta, int N) {
    int i = blockIdx.x * blockDim.x + threadIdx.x;
    if (i > 0 && i < NPIDMAX) {
        unsigned long long key = g_best[i];
        if (key != 0ULL) {
            int idx = (int)(0xFFFFFFFFu - (unsigned)(key & 0xFFFFFFFFull));
            int pos = atomicAdd(&g_cpcount, 1);
            g_cplist[pos] = idx;
        }
    }
    float va = 0.0f; int m = 0;
    if (i < N) {
        int p = pid[i];
        if (p > 0 && pt[i] > 0.9f && recon[i] > 0 && fabsf(eta[i]) < 4.0f) {
            unsigned long long key = g_best[p];
            int a = (int)(0xFFFFFFFFu - (unsigned)(key & 0xFFFFFFFFull));
            const float4* xi = (const float4*)(x + (size_t)i * 8);
            const float4* xa = (const float4*)(x + (size_t)a * 8);
            float4 i0 = xi[0], i1 = xi[1], a0 = xa[0], a1 = xa[1];
            float d, d2 = 0.0f;
            d = i0.x - a0.x; d2 += d * d;
            d = i0.y - a0.y; d2 += d * d;
            d = i0.z - a0.z; d2 += d * d;
            d = i0.w - a0.w; d2 += d * d;
            d = i1.x - a1.x; d2 += d * d;
            d = i1.y - a1.y; d2 += d * d;
            d = i1.z - a1.z; d2 += d * d;
            d = i1.w - a1.w; d2 += d * d;
            va = d2 * g_q[i] * g_q[a];
            m = 1;
        }
    }
    #pragma unroll
    for (int o = 16; o; o >>= 1) {
        va += __shfl_down_sync(0xFFFFFFFFu, va, o);
        m  += __shfl_down_sync(0xFFFFFFFFu, m,  o);
    }
    if ((threadIdx.x & 31) == 0 && (m || va != 0.0f)) {
        atomicAdd(&g_att, (double)va);
        atomicAdd(&g_maskcnt, m);
    }
}

// scaled distance chain: D2 = 256*d2 (m2x = -512*xc, n2cs = 256*|xc|^2)
#define D2_CHAIN(res, V0, V1, N2J, c)                 \
    float res = fmaf(V0.x, m2x[c][0], n2cs[c]);       \
    res = fmaf(V0.y, m2x[c][1], res);                 \
    res = fmaf(V0.z, m2x[c][2], res);                 \
    res = fmaf(V0.w, m2x[c][3], res);                 \
    res = fmaf(V1.x, m2x[c][4], res);                 \
    res = fmaf(V1.y, m2x[c][5], res);                 \
    res = fmaf(V1.z, m2x[c][6], res);                 \
    res = fmaf(V1.w, m2x[c][7], res);                 \
    res = fmaf(N2J, 256.0f, res);

// ---- repulsion: branchless pass A histogram; predicated pass B; unroll-2 ----
__global__ void __launch_bounds__(RT, 3) k_repulse(const int* __restrict__ pid, int N) {
    __shared__ int      s_hist[CPT][NB];
    __shared__ int      s_Bs[CPT];
    __shared__ int      s_rs[CPT];
    __shared__ int      s_bcnt[CPT];
    __shared__ unsigned s_bk[CPT][BCAP];
    __shared__ float    s_bw[CPT][BCAP];
    __shared__ float    s_qc[CPT];
    __shared__ float    s_red[RT / 32];

    int tid   = threadIdx.x;
    int ncp   = g_cpcount;
    int cbase = blockIdx.x * CPT;
    if (cbase >= ncp) return;

    float m2x[CPT][8], n2cs[CPT];
    int   pidc[CPT];
    #pragma unroll
    for (int c = 0; c < CPT; c++) {
        int slot = cbase + c;
        bool act = slot < ncp;
        int ci = act ? g_cplist[slot] : 0;
        float4 p0 = g_xp[2 * ci + 0];
        float4 p1 = g_xp[2 * ci + 1];
        m2x[c][0] = -512.0f * p0.x; m2x[c][1] = -512.0f * p0.y;
        m2x[c][2] = -512.0f * p0.z; m2x[c][3] = -512.0f * p0.w;
        m2x[c][4] = -512.0f * p1.x; m2x[c][5] = -512.0f * p1.y;
        m2x[c][6] = -512.0f * p1.z; m2x[c][7] = -512.0f * p1.w;
        n2cs[c] = act ? 256.0f * g_n2[ci] : 1e30f;
        pidc[c] = act ? pid[ci]  : -1;
        if (tid == 0) s_qc[c] = act ? g_q[ci] : 0.0f;
    }

    for (int h = tid; h < CPT * NB; h += RT) ((int*)s_hist)[h] = 0;
    if (tid < CPT) s_bcnt[tid] = 0;
    __syncthreads();

    unsigned histbase[CPT];
    #pragma unroll
    for (int c = 0; c < CPT; c++)
        histbase[c] = (unsigned)__cvta_generic_to_shared(&s_hist[c][0]);

    // ---- Pass A: branchless count histogram, 2 j's per iteration ----
    for (int j = tid; j < N; j += 2 * RT) {
        int j2 = j + RT;                 // N/(2RT) exact: j2 always in range
        float4 a0 = g_xp[2 * j + 0];
        float4 a1 = g_xp[2 * j + 1];
        float4 b0 = g_xp[2 * j2 + 0];
        float4 b1 = g_xp[2 * j2 + 1];
        float n2a = g_n2[j];
        float n2b = g_n2[j2];
        #pragma unroll
        for (int c = 0; c < CPT; c++) {
            D2_CHAIN(Da, a0, a1, n2a, c)
            D2_CHAIN(Db, b0, b1, n2b, c)
            int ba = min((int)fmaxf(Da, 0.0f), NB - 1);
            int bb = min((int)fmaxf(Db, 0.0f), NB - 1);
            hist_add(histbase[c] + (unsigned)(ba << 2), Da);
            hist_add(histbase[c] + (unsigned)(bb << 2), Db);
        }
    }
    __syncthreads();

    // ---- selection: boundary bin B and residual r per CP ----
    if (tid < CPT) {
        int cum = 0, B = NB, r = 0;
        for (int b = 0; b < NB; b++) {
            int nc = cum + s_hist[tid][b];
            if (nc >= KSEL2) { B = b; r = KSEL2 - cum; break; }
            cum = nc;
        }
        s_Bs[tid] = B; s_rs[tid] = r;
    }
    __syncthreads();

    int Breg[CPT];
    #pragma unroll
    for (int c = 0; c < CPT; c++) Breg[c] = s_Bs[c];

    // ---- Pass B: predicated accumulate (< B); rare boundary gather; unroll-2 ----
    float acc[CPT];
    #pragma unroll
    for (int c = 0; c < CPT; c++) acc[c] = 0.0f;

    for (int j = tid; j < N; j += 2 * RT) {
        int j2 = j + RT;
        float4 a0 = g_xp[2 * j + 0];
        float4 a1 = g_xp[2 * j + 1];
        float4 b0 = g_xp[2 * j2 + 0];
        float4 b1 = g_xp[2 * j2 + 1];
        float n2a = g_n2[j];
        float n2b = g_n2[j2];
        float qa  = g_q[j];
        float qb  = g_q[j2];
        int   pa  = pid[j];
        int   pb  = pid[j2];
        bool anyB = false;
        float dsa[CPT], dsb[CPT];
        #pragma unroll
        for (int c = 0; c < CPT; c++) {
            D2_CHAIN(Da, a0, a1, n2a, c)
            D2_CHAIN(Db, b0, b1, n2b, c)
            dsa[c] = Da; dsb[c] = Db;
            float Dac = fmaxf(Da, 0.0f);
            float Dbc = fmaxf(Db, 0.0f);
            int ba = min((int)Dac, NB - 1);
            int bb = min((int)Dbc, NB - 1);
            float wa = fmaf(-0.0625f, sqrtf(Dac), 1.0f) * qa;
            float wb = fmaf(-0.0625f, sqrtf(Dbc), 1.0f) * qb;
            bool sa = (Da <= 256.0f) && (ba < Breg[c]) && (pa != pidc[c]);
            bool sb = (Db <= 256.0f) && (bb < Breg[c]) && (pb != pidc[c]);
            acc[c] += sa ? wa : 0.0f;
            acc[c] += sb ? wb : 0.0f;
            anyB |= (Da <= 256.0f) && (ba == Breg[c]);
            anyB |= (Db <= 256.0f) && (bb == Breg[c]);
        }
        if (__any_sync(0xFFFFFFFFu, anyB)) {
            #pragma unroll
            for (int c = 0; c < CPT; c++) {
                float Da = dsa[c];
                if (Da <= 256.0f) {
                    float Dac = fmaxf(Da, 0.0f);
                    int ba = min((int)Dac, NB - 1);
                    if (ba == Breg[c]) {
                        float w = (pa != pidc[c]) ? fmaf(-0.0625f, sqrtf(Dac), 1.0f) * qa : 0.0f;
                        int p = atomicAdd(&s_bcnt[c], 1);
                        if (p < BCAP) { s_bk[c][p] = __float_as_uint(Dac); s_bw[c][p] = w; }
                    }
                }
                float Db = dsb[c];
                if (Db <= 256.0f) {
                    float Dbc = fmaxf(Db, 0.0f);
                    int bb = min((int)Dbc, NB - 1);
                    if (bb == Breg[c]) {
                        float w = (pb != pidc[c]) ? fmaf(-0.0625f, sqrtf(Dbc), 1.0f) * qb : 0.0f;
                        int p = atomicAdd(&s_bcnt[c], 1);
                        if (p < BCAP) { s_bk[c][p] = __float_as_uint(Dbc); s_bw[c][p] = w; }
                    }
                }
            }
        }
    }
    __syncthreads();

    // ---- boundary mini-rank + per-CP reduction ----
    #pragma unroll
    for (int c = 0; c < CPT; c++) {
        float part = acc[c];
        int m = min(s_bcnt[c], BCAP);
        int r = s_rs[c];
        if (r > 0) {
            for (int e = tid; e < m; e += RT) {
                unsigned ke = s_bk[c][e];
                int rank = 0;
                for (int k = 0; k < m; k++) {
                    unsigned kk = s_bk[c][k];
                    rank += (kk < ke) || (kk == ke && k < e);
                }
                if (rank < r) part += s_bw[c][e];
            }
        }
        #pragma unroll
        for (int o = 16; o; o >>= 1) part += __shfl_down_sync(0xFFFFFFFFu, part, o);
        if ((tid & 31) == 0) s_red[tid >> 5] = part;
        __syncthreads();
        if (tid == 0) {
            float tot = 0.0f;
            #pragma unroll
            for (int w = 0; w < RT / 32; w++) tot += s_red[w];
            if (tot != 0.0f) atomicAdd(&g_rep, (double)(tot * s_qc[c]));
        }
        __syncthreads();
    }
}

__global__ void k_final(float* out, int N) {
    if (blockIdx.x == 0 && threadIdx.x == 0) {
        int mc = g_maskcnt;
        out[0] = (float)(mc > 0 ? g_att / (double)mc : 0.0);
        out[1] = (float)(g_rep / (double)N);
        out[2] = 0.0f;
        out[3] = 0.0f;
    }
}

extern "C" void kernel_launch(void* const* d_in, const int* in_sizes, int n_in,
                              void* d_out, int out_size) {
    const float* beta  = (const float*)d_in[0];
    const float* x     = (const float*)d_in[1];
    const int*   pid   = (const int*)d_in[2];
    const int*   recon = (const int*)d_in[3];
    const float* pt    = (const float*)d_in[4];
    const float* eta   = (const float*)d_in[5];
    float* out = (float*)d_out;
    int N = in_sizes[0];

    k_init<<<(NPIDMAX + 255) / 256, 256>>>();
    k_bestq<<<(N + 255) / 256, 256>>>(beta, pid, x, N);
    k_attract<<<(N + 127) / 128, 128>>>(x, pid, recon, pt, eta, N);
    int ngrp = (NPIDMAX + CPT - 1) / CPT;   // 512 blocks
    k_repulse<<<ngrp, RT>>>(pid, N);
    k_final<<<1, 32>>>(out, N);
}